// round 14
// baseline (speedup 1.0000x reference)
#include <cuda_runtime.h>
#include <cuda_bf16.h>
#include <cstdint>

// ---------------- problem constants ----------------
constexpr int B    = 8;
constexpr int C    = 5;
constexpr int NN   = 512;
constexpr int FIN  = 768;
constexpr int H    = 4;
constexpr int DHID = 128;
constexpr int DOUT = 64;
constexpr int HD   = H * DHID;   // 512
constexpr int HD2  = H * DOUT;   // 256
constexpr int BC   = B * C;      // 40

// ---------------- scratch ----------------
// i-pair packed feat (gemm out -> agg B): [bc][u=NN/2][Nn<=HD]
__device__ __align__(256) uint32_t g_fhi[(size_t)BC * (NN / 2) * HD];
__device__ __align__(256) uint32_t g_flo[(size_t)BC * (NN / 2) * HD];
// d-pair packed h (agg out -> gemm A): [bc][m=NN][HD/2]
__device__ __align__(256) uint32_t g_hhi[(size_t)BC * NN * (HD / 2)];
__device__ __align__(256) uint32_t g_hlo[(size_t)BC * NN * (HD / 2)];
// d-pair packed x[:,0]: [b][n][FIN/2]
__device__ __align__(256) uint32_t g_xhi[(size_t)B * NN * (FIN / 2)];
__device__ __align__(256) uint32_t g_xlo[(size_t)B * NN * (FIN / 2)];
__device__ __align__(256) float g_out2[(size_t)BC * NN * HD2];
__device__ __align__(256) float g_elr [2 * BC * H * NN];

// ---------------- bf16 helpers ----------------
__device__ __forceinline__ uint32_t packbf2(float hi, float lo) {
    uint32_t d;
    asm("cvt.rn.bf16x2.f32 %0, %1, %2;" : "=r"(d) : "f"(hi), "f"(lo));
    return d;
}
__device__ __forceinline__ float bflo(uint32_t u) { return __uint_as_float(u << 16); }
__device__ __forceinline__ float bfhi(uint32_t u) { return __uint_as_float(u & 0xffff0000u); }

__device__ __forceinline__ void mma_bf16(float* d, const uint32_t* a, const uint32_t* b) {
    asm volatile(
        "mma.sync.aligned.m16n8k16.row.col.f32.bf16.bf16.f32 "
        "{%0,%1,%2,%3}, {%4,%5,%6,%7}, {%8,%9}, {%0,%1,%2,%3};\n"
        : "+f"(d[0]), "+f"(d[1]), "+f"(d[2]), "+f"(d[3])
        : "r"(a[0]), "r"(a[1]), "r"(a[2]), "r"(a[3]), "r"(b[0]), "r"(b[1]));
}

__device__ __forceinline__ void cp16(uint32_t smem_dst, const void* gsrc) {
    asm volatile("cp.async.ca.shared.global [%0], [%1], 16;\n"
                 :: "r"(smem_dst), "l"(gsrc));
}

// ---------------- x pre-pack: d-pairs hi/lo ----------------
__global__ void split_x(const float* __restrict__ x,
                        uint32_t* __restrict__ hi, uint32_t* __restrict__ lo) {
    int idx = blockIdx.x * 256 + threadIdx.x;
    if (idx >= B * NN * (FIN / 2)) return;
    int kp = idx % (FIN / 2);
    int n  = (idx / (FIN / 2)) % NN;
    int b  = idx / (NN * (FIN / 2));
    const float* p = x + ((size_t)b * C * NN + n) * FIN + 2 * kp;
    float v0 = p[0], v1 = p[1];
    uint32_t h = packbf2(v1, v0);
    hi[idx] = h;
    lo[idx] = packbf2(v1 - bfhi(h), v0 - bflo(h));
}

// ---------------- gemm smem geometry ----------------
constexpr int BP    = 132;            // B pitch (f32): (8tg+gr)%32 conflict-free
constexpr int A_ST  = 128 * 8;        // per plane (u32), pitch 8: (8gr+tg)%32 c-f
constexpr int STG   = 2 * A_ST + 16 * BP;   // 4160 u32
constexpr int GEMM_SMEM = 3 * STG * 4;      // 49920 B

// ---------------- bf16 GEMM: pre-packed A planes, runtime-split W ----------
// out: i-pair packed feat hi/lo + fused el/er.
__global__ __launch_bounds__(256, 2) void gemm_tc(
    const uint32_t* __restrict__ Ahi, const uint32_t* __restrict__ Alo,
    const float* __restrict__ W,
    uint32_t* __restrict__ Fhi, uint32_t* __restrict__ Flo,
    int K, int Nn, size_t aSB, size_t aSC,
    const float* __restrict__ al, const float* __restrict__ ar,
    float* __restrict__ elo, float* __restrict__ ero, int Dh) {
    extern __shared__ float sm[];

    int bc = blockIdx.z;
    int b  = bc / C, c = bc % C;
    int Kp = K / 2;
    const uint32_t* AbH = Ahi + (size_t)b * aSB + (size_t)c * aSC;
    const uint32_t* AbL = Alo + (size_t)b * aSB + (size_t)c * aSC;
    const float* Wc = W + (size_t)c * K * Nn;
    uint32_t* FhB = Fhi + (size_t)bc * (NN / 2) * Nn;
    uint32_t* FlB = Flo + (size_t)bc * (NN / 2) * Nn;

    int m0 = blockIdx.y * 128, n0c = blockIdx.x * 128;
    int tid  = threadIdx.x;
    int lane = tid & 31, warp = tid >> 5;
    int wm = warp & 1, wn = warp >> 1;
    int gr = lane >> 2, tg = lane & 3;

    uint32_t smem_base = (uint32_t)__cvta_generic_to_shared(sm);

    int arow = tid >> 1, aoff = (tid & 1) * 4;
    int bk0 = tid >> 5,  bnq = (tid & 31) * 4;
    int bk1 = (tid + 256) >> 5;

    auto issue_stage = [&](int st, int t) {
        uint32_t hB = smem_base + (st * STG) * 4;
        uint32_t lB = hB + A_ST * 4;
        uint32_t bB = lB + A_ST * 4;
        size_t ga = (size_t)(m0 + arow) * Kp + t * 8 + aoff;
        cp16(hB + (arow * 8 + aoff) * 4, AbH + ga);
        cp16(lB + (arow * 8 + aoff) * 4, AbL + ga);
        const float* Wct = Wc + (size_t)(t * 16) * Nn + n0c;
        cp16(bB + (bk0 * BP + bnq) * 4, Wct + (size_t)bk0 * Nn + bnq);
        cp16(bB + (bk1 * BP + bnq) * 4, Wct + (size_t)bk1 * Nn + bnq);
    };

    float acc[4][4][4] = {};

    auto compute_stage = [&](int st) {
        const uint32_t* AhS = (const uint32_t*)sm + st * STG;
        const uint32_t* AlS = AhS + A_ST;
        const float* Bs = (const float*)(AlS + A_ST);
        uint32_t ah[4][4], alo[4][4], bh[4][2], bl[4][2];
#pragma unroll
        for (int mt = 0; mt < 4; mt++) {
            int m = wm * 64 + mt * 16 + gr;
            ah[mt][0]  = AhS[m * 8 + tg];
            ah[mt][1]  = AhS[(m + 8) * 8 + tg];
            ah[mt][2]  = AhS[m * 8 + tg + 4];
            ah[mt][3]  = AhS[(m + 8) * 8 + tg + 4];
            alo[mt][0] = AlS[m * 8 + tg];
            alo[mt][1] = AlS[(m + 8) * 8 + tg];
            alo[mt][2] = AlS[m * 8 + tg + 4];
            alo[mt][3] = AlS[(m + 8) * 8 + tg + 4];
        }
#pragma unroll
        for (int nt = 0; nt < 4; nt++) {
            int n = wn * 32 + nt * 8 + gr;
            const float* wb = Bs + 2 * tg * BP + n;
            float w0 = wb[0], w1 = wb[BP], w2 = wb[8 * BP], w3 = wb[9 * BP];
            bh[nt][0] = packbf2(w1, w0);
            bh[nt][1] = packbf2(w3, w2);
            bl[nt][0] = packbf2(w1 - bfhi(bh[nt][0]), w0 - bflo(bh[nt][0]));
            bl[nt][1] = packbf2(w3 - bfhi(bh[nt][1]), w2 - bflo(bh[nt][1]));
        }
#pragma unroll
        for (int mt = 0; mt < 4; mt++)
#pragma unroll
            for (int nt = 0; nt < 4; nt++) {
                mma_bf16(acc[mt][nt], ah[mt], bh[nt]);
                mma_bf16(acc[mt][nt], alo[mt], bh[nt]);
                mma_bf16(acc[mt][nt], ah[mt], bl[nt]);
            }
    };

    int T = K / 16;
    issue_stage(0, 0);
    asm volatile("cp.async.commit_group;\n" ::);
    issue_stage(1, 1);
    asm volatile("cp.async.commit_group;\n" ::);

    for (int i = 0; i < T; i++) {
        asm volatile("cp.async.wait_group 1;\n" ::);
        __syncthreads();
        if (i + 2 < T) issue_stage((i + 2) % 3, i + 2);
        asm volatile("cp.async.commit_group;\n" ::);
        compute_stage(i % 3);
    }

    // ---- epilogue: i-pair packed feat + fused el/er ----
    int head  = (n0c + wn * 32) / Dh;
    int dbase = n0c + wn * 32 - head * Dh;
    const float* alh = al + ((size_t)c * H + head) * Dh;
    const float* arh = ar + ((size_t)c * H + head) * Dh;
    float* elh = elo + ((size_t)bc * H + head) * NN;
    float* erh = ero + ((size_t)bc * H + head) * NN;

#pragma unroll
    for (int mt = 0; mt < 4; mt++) {
        float el0 = 0.f, el1 = 0.f, er0 = 0.f, er1 = 0.f;
#pragma unroll
        for (int nt = 0; nt < 4; nt++) {
            float o0 = acc[mt][nt][0], o1 = acc[mt][nt][1];
            float o2 = acc[mt][nt][2], o3 = acc[mt][nt][3];
            // neighbor-row values (gr^1 lives at lane^4)
            float q0 = __shfl_xor_sync(0xffffffffu, o0, 4);
            float q1 = __shfl_xor_sync(0xffffffffu, o1, 4);
            float q2 = __shfl_xor_sync(0xffffffffu, o2, 4);
            float q3 = __shfl_xor_sync(0xffffffffu, o3, 4);
            if (!(gr & 1)) {
                int r = m0 + wm * 64 + mt * 16 + gr;
                int u = r >> 1;
                int col = n0c + wn * 32 + nt * 8 + tg * 2;
                uint32_t h0 = packbf2(q0, o0), h1 = packbf2(q1, o1);
                uint32_t l0 = packbf2(q0 - bfhi(h0), o0 - bflo(h0));
                uint32_t l1 = packbf2(q1 - bfhi(h1), o1 - bflo(h1));
                *(uint2*)(FhB + (size_t)u * Nn + col) = make_uint2(h0, h1);
                *(uint2*)(FlB + (size_t)u * Nn + col) = make_uint2(l0, l1);
                uint32_t h2 = packbf2(q2, o2), h3 = packbf2(q3, o3);
                uint32_t l2 = packbf2(q2 - bfhi(h2), o2 - bflo(h2));
                uint32_t l3 = packbf2(q3 - bfhi(h3), o3 - bflo(h3));
                *(uint2*)(FhB + (size_t)(u + 4) * Nn + col) = make_uint2(h2, h3);
                *(uint2*)(FlB + (size_t)(u + 4) * Nn + col) = make_uint2(l2, l3);
            }
            int d = dbase + nt * 8 + tg * 2;
            float a0 = alh[d], a1 = alh[d + 1];
            float r0 = arh[d], r1 = arh[d + 1];
            el0 += o0 * a0 + o1 * a1;
            el1 += o2 * a0 + o3 * a1;
            er0 += o0 * r0 + o1 * r1;
            er1 += o2 * r0 + o3 * r1;
        }
#pragma unroll
        for (int o = 1; o < 4; o <<= 1) {
            el0 += __shfl_xor_sync(0xffffffffu, el0, o);
            el1 += __shfl_xor_sync(0xffffffffu, el1, o);
            er0 += __shfl_xor_sync(0xffffffffu, er0, o);
            er1 += __shfl_xor_sync(0xffffffffu, er1, o);
        }
        if (tg == 0) {
            int row = m0 + wm * 64 + mt * 16 + gr;
            atomicAdd(elh + row,     el0);
            atomicAdd(elh + row + 8, el1);
            atomicAdd(erh + row,     er0);
            atomicAdd(erh + row + 8, er1);
        }
    }
}

// ================= agg v2 (D=128, JT=128): pre-packed p AND f fragments =================
// out: d-pair packed hi/lo (next layer's gemm A).
template <bool RELU>
__global__ __launch_bounds__(256, 2) void agg_tc2(
    const float* __restrict__ adj,
    const uint32_t* __restrict__ fhi_g,
    const uint32_t* __restrict__ flo_g,
    const float* __restrict__ el,
    const float* __restrict__ er,
    const float* __restrict__ bias,
    uint32_t* __restrict__ outHi,
    uint32_t* __restrict__ outLo) {
    constexpr int D  = 128, JT = 128;
    constexpr int PPK = 136;          // packed-p pitch: (8tg+gr)%32 conflict-free
    constexpr int FPK = 136;          // packed-f pitch
    constexpr int ADJ_ST = 16 * JT;
    constexpr int F_ST   = 8 * FPK;   // per plane, 8 u-rows
    constexpr int PK_ST  = 8 * PPK;
    constexpr int T = NN / 16;
    constexpr int NC = HD;            // packed feat row width (u32)

    extern __shared__ float sm[];
    float* el_s  = sm;                              // 512
    float* er_s  = el_s + NN;                       // 128
    float* m_s   = er_s + JT;                       // 128
    float* sc_s  = m_s + JT;                        // 128
    float* red   = sc_s + JT;                       // 8
    float* s_red = red + 8;                         // 256
    float* adj_s = s_red + 2 * JT;                  // 4*2048
    uint32_t* fhi_s = (uint32_t*)(adj_s + 4 * ADJ_ST);   // 4*F_ST
    uint32_t* flo_s = fhi_s + 4 * F_ST;                  // 4*F_ST
    uint32_t* p_pk  = flo_s + 4 * F_ST;                  // 2*PK_ST

    int bc = blockIdx.z, h = blockIdx.y;
    int c = bc % C;
    int j0 = blockIdx.x * JT;
    int tid = threadIdx.x;
    int lane = tid & 31, warp = tid >> 5;
    int jm = warp & 1, dn = warp >> 1;
    int gr = lane >> 2, tg = lane & 3;

    const float* adj_bc = adj + (size_t)bc * NN * NN;
    const float* elh = el + (size_t)(bc * H + h) * NN;
    const float* erh = er + (size_t)(bc * H + h) * NN;
    const uint32_t* fh_g = fhi_g + (size_t)bc * (NN / 2) * NC + h * D;
    const uint32_t* fl_g = flo_g + (size_t)bc * (NN / 2) * NC + h * D;

    uint32_t smem_u32 = (uint32_t)__cvta_generic_to_shared(sm);
    uint32_t adj_u32  = smem_u32 + (uint32_t)((adj_s - sm) * 4);
    uint32_t fhi_u32  = smem_u32 + (uint32_t)((float*)fhi_s - sm) * 4;
    uint32_t flo_u32  = smem_u32 + (uint32_t)((float*)flo_s - sm) * 4;

    auto issue_stage = [&](int st, int t) {
        uint32_t aB = adj_u32 + st * ADJ_ST * 4;
#pragma unroll
        for (int l = 0; l < 2; l++) {
            int s = tid + l * 256;
            int r = s >> 5, cq = s & 31;
            cp16(aB + (r * JT + cq * 4) * 4,
                 adj_bc + (size_t)(t * 16 + r) * NN + j0 + cq * 4);
        }
        {   // feat: 8 u-rows x 32 chunks per plane, 1/thread/plane
            int r = tid >> 5, cq = tid & 31;
            size_t g = (size_t)(t * 8 + r) * NC + cq * 4;
            cp16(fhi_u32 + (st * F_ST + r * FPK + cq * 4) * 4, fh_g + g);
            cp16(flo_u32 + (st * F_ST + r * FPK + cq * 4) * 4, fl_g + g);
        }
    };

    float e0 = elh[tid], e1 = elh[tid + 256];
    el_s[tid] = e0; el_s[tid + 256] = e1;
    if (tid < JT) er_s[tid] = erh[j0 + tid];

    issue_stage(0, 0);
    asm volatile("cp.async.commit_group;\n" ::);
    issue_stage(1, 1);
    asm volatile("cp.async.commit_group;\n" ::);
    issue_stage(2, 2);
    asm volatile("cp.async.commit_group;\n" ::);

    float v = fmaxf(e0, e1);
#pragma unroll
    for (int o = 16; o; o >>= 1) v = fmaxf(v, __shfl_xor_sync(0xffffffffu, v, o));
    if (lane == 0) red[warp] = v;
    __syncthreads();
    if (tid == 0) {
        float m = red[0];
#pragma unroll
        for (int w = 1; w < 8; w++) m = fmaxf(m, red[w]);
        red[0] = m;
    }
    __syncthreads();
    if (tid < JT) {
        float e = red[0] + er_s[tid];
        m_s[tid] = e > 0.f ? e : 0.2f * e;
    }

    int pj  = tid % JT;
    int pi0 = tid / JT;
    float s_priv = 0.f;

    auto produce = [&](int t) {
        const float* a_st = adj_s + (t % 4) * ADJ_ST;
        uint32_t* p_nb = p_pk + (t & 1) * PK_ST;
#pragma unroll
        for (int q = 0; q < 4; q++) {
            int u = pi0 * 4 + q;
            float a0 = a_st[(2 * u) * JT + pj];
            float a1 = a_st[(2 * u + 1) * JT + pj];
            float p0 = 0.f, p1 = 0.f;
            if (a0 > 0.f) {
                float e = el_s[t * 16 + 2 * u] + er_s[pj];
                e = e > 0.f ? e : 0.2f * e;
                p0 = __expf(e - m_s[pj]);
            }
            if (a1 > 0.f) {
                float e = el_s[t * 16 + 2 * u + 1] + er_s[pj];
                e = e > 0.f ? e : 0.2f * e;
                p1 = __expf(e - m_s[pj]);
            }
            uint32_t pk = packbf2(p1, p0);
            s_priv += bflo(pk) + bfhi(pk);
            p_nb[u * PPK + pj] = pk;
        }
    };

    asm volatile("cp.async.wait_group 2;\n" ::);
    __syncthreads();
    produce(0);

    float acc[4][4][4] = {};

    for (int i = 0; i < T; i++) {
        asm volatile("cp.async.wait_group 1;\n" ::);
        __syncthreads();

        const uint32_t* fh = fhi_s + (i % 4) * F_ST;
        const uint32_t* fl = flo_s + (i % 4) * F_ST;
        const uint32_t* p_buf = p_pk + (i & 1) * PK_ST;

        uint32_t pa[4][4];
#pragma unroll
        for (int mt = 0; mt < 4; mt++) {
            int jb = jm * 64 + mt * 16 + gr;
            const uint32_t* pb = p_buf + tg * PPK + jb;
            pa[mt][0] = pb[0];
            pa[mt][1] = pb[8];
            pa[mt][2] = pb[4 * PPK];
            pa[mt][3] = pb[4 * PPK + 8];
        }
#pragma unroll
        for (int nt = 0; nt < 4; nt++) {
            int db = dn * 32 + nt * 8 + gr;
            uint32_t bh[2], bl[2];
            bh[0] = fh[tg * FPK + db];
            bh[1] = fh[(tg + 4) * FPK + db];
            bl[0] = fl[tg * FPK + db];
            bl[1] = fl[(tg + 4) * FPK + db];
#pragma unroll
            for (int mt = 0; mt < 4; mt++) {
                mma_bf16(acc[mt][nt], pa[mt], bh);
                mma_bf16(acc[mt][nt], pa[mt], bl);
            }
        }

        if (i + 1 < T) produce(i + 1);

        if (i + 3 < T) issue_stage((i + 3) % 4, i + 3);
        asm volatile("cp.async.commit_group;\n" ::);
    }

    s_red[pi0 * JT + pj] = s_priv;
    __syncthreads();
    if (tid < JT)
        sc_s[tid] = 1.0f / fmaxf(s_red[tid] + s_red[JT + tid], 1e-9f);
    __syncthreads();

    // ---- epilogue: d-pair packed hi/lo output ----
    uint32_t* oh = outHi + (size_t)bc * NN * (HD / 2);
    uint32_t* ol = outLo + (size_t)bc * NN * (HD / 2);
    const float* bh_ = bias + (size_t)c * (H * D) + h * D;
    int kpb = h * (D / 2);
#pragma unroll
    for (int mt = 0; mt < 4; mt++) {
#pragma unroll
        for (int nt = 0; nt < 4; nt++) {
            int jl = jm * 64 + mt * 16 + gr;
            int d  = dn * 32 + nt * 8 + tg * 2;
            float bb0 = bh_[d], bb1 = bh_[d + 1];
            float sc0 = sc_s[jl], sc1 = sc_s[jl + 8];
            float o0 = acc[mt][nt][0] * sc0 + bb0;
            float o1 = acc[mt][nt][1] * sc0 + bb1;
            float o2 = acc[mt][nt][2] * sc1 + bb0;
            float o3 = acc[mt][nt][3] * sc1 + bb1;
            if (RELU) {
                o0 = fmaxf(o0, 0.f); o1 = fmaxf(o1, 0.f);
                o2 = fmaxf(o2, 0.f); o3 = fmaxf(o3, 0.f);
            }
            int kp = kpb + (d >> 1);
            int j = j0 + jl;
            uint32_t h0 = packbf2(o1, o0);
            uint32_t h1 = packbf2(o3, o2);
            oh[(size_t)j * (HD / 2) + kp]       = h0;
            oh[(size_t)(j + 8) * (HD / 2) + kp] = h1;
            ol[(size_t)j * (HD / 2) + kp]       = packbf2(o1 - bfhi(h0), o0 - bflo(h0));
            ol[(size_t)(j + 8) * (HD / 2) + kp] = packbf2(o3 - bfhi(h1), o2 - bflo(h1));
        }
    }
}

constexpr int AGG2_SMEM =
    (NN + 3 * 128 + 8 + 2 * 128 + 4 * 16 * 128 + 8 * (8 * 136) + 2 * 8 * 136) * 4;  // 80928

// ================= agg v1 (layer 2: D=64, JT=256): packed p + packed f, f32 out ==========
template <int D, int JT, bool RELU>
__global__ __launch_bounds__(256) void agg_tc(
    const float* __restrict__ adj,
    const uint32_t* __restrict__ fhi_g,
    const uint32_t* __restrict__ flo_g,
    const float* __restrict__ el,
    const float* __restrict__ er,
    const float* __restrict__ bias,
    float* __restrict__ out) {
    constexpr int PPK = JT + 8;       // 264
    constexpr int FPK = D + 8;        // 72: (8tg+gr)%32 conflict-free
    constexpr int WJ = JT / 64;
    constexpr int ADJ_ST = 16 * JT;
    constexpr int F_ST   = 8 * FPK;
    constexpr int PK_ST  = 8 * PPK;
    constexpr int NC = HD2;           // 256

    extern __shared__ float sm[];
    float* el_s  = sm;
    float* er_s  = el_s + NN;
    float* m_s   = er_s + JT;
    float* sc_s  = m_s + JT;
    float* red   = sc_s + JT;
    float* s_red = red + 8;
    float* adj_s = s_red + JT;
    uint32_t* fhi_s = (uint32_t*)(adj_s + 3 * ADJ_ST);
    uint32_t* flo_s = fhi_s + 3 * F_ST;
    uint32_t* p_pk  = flo_s + 3 * F_ST;

    int bc = blockIdx.z, h = blockIdx.y;
    int c = bc % C;
    int j0 = blockIdx.x * JT;
    int tid = threadIdx.x;
    int lane = tid & 31, warp = tid >> 5;
    int jm = warp % WJ, dn = warp / WJ;
    int gr = lane >> 2, tg = lane & 3;

    const float* adj_bc = adj + (size_t)bc * NN * NN;
    const float* elh = el + (size_t)(bc * H + h) * NN;
    const float* erh = er + (size_t)(bc * H + h) * NN;
    const uint32_t* fh_g = fhi_g + (size_t)bc * (NN / 2) * NC + h * D;
    const uint32_t* fl_g = flo_g + (size_t)bc * (NN / 2) * NC + h * D;

    uint32_t smem_u32 = (uint32_t)__cvta_generic_to_shared(sm);
    uint32_t adj_u32  = smem_u32 + (uint32_t)((adj_s - sm) * 4);
    uint32_t fhi_u32  = smem_u32 + (uint32_t)((float*)fhi_s - sm) * 4;
    uint32_t flo_u32  = smem_u32 + (uint32_t)((float*)flo_s - sm) * 4;

    auto issue_stage = [&](int st, int t) {
        uint32_t aB = adj_u32 + st * ADJ_ST * 4;
#pragma unroll
        for (int l = 0; l < 4; l++) {
            int s = tid + l * 256;
            int r = s >> 6, cq = s & 63;
            cp16(aB + (r * JT + cq * 4) * 4,
                 adj_bc + (size_t)(t * 16 + r) * NN + j0 + cq * 4);
        }
        {   // feat: 8 u-rows x 16 chunks per plane; 256 threads -> half do hi, half lo
            int s = tid & 127;
            int r = s >> 4, cq = s & 15;
            size_t g = (size_t)(t * 8 + r) * NC + cq * 4;
            if (tid < 128)
                cp16(fhi_u32 + (st * F_ST + r * FPK + cq * 4) * 4, fh_g + g);
            else
                cp16(flo_u32 + (st * F_ST + r * FPK + cq * 4) * 4, fl_g + g);
        }
    };

    float e0 = elh[tid], e1 = elh[tid + 256];
    el_s[tid] = e0; el_s[tid + 256] = e1;
#pragma unroll
    for (int t = tid; t < JT; t += 256) er_s[t] = erh[j0 + t];

    issue_stage(0, 0);
    asm volatile("cp.async.commit_group;\n" ::);
    issue_stage(1, 1);
    asm volatile("cp.async.commit_group;\n" ::);

    float v = fmaxf(e0, e1);
#pragma unroll
    for (int o = 16; o; o >>= 1) v = fmaxf(v, __shfl_xor_sync(0xffffffffu, v, o));
    if (lane == 0) red[warp] = v;
    __syncthreads();
    if (tid == 0) {
        float m = red[0];
#pragma unroll
        for (int w = 1; w < 8; w++) m = fmaxf(m, red[w]);
        red[0] = m;
    }
    __syncthreads();
#pragma unroll
    for (int t = tid; t < JT; t += 256) {
        float e = red[0] + er_s[t];
        m_s[t] = e > 0.f ? e : 0.2f * e;
    }

    int pj = tid;   // JT == 256

    float acc[4][4][4] = {};
    float s_priv = 0.f;

    constexpr int T = NN / 16;
    for (int i = 0; i < T; i++) {
        asm volatile("cp.async.wait_group 1;\n" ::);
        __syncthreads();

        const float* a_st = adj_s + (i % 3) * ADJ_ST;
        uint32_t* p_buf = p_pk + (i & 1) * PK_ST;
#pragma unroll
        for (int u = 0; u < 8; u++) {
            float a0 = a_st[(2 * u) * JT + pj];
            float a1 = a_st[(2 * u + 1) * JT + pj];
            float p0 = 0.f, p1 = 0.f;
            if (a0 > 0.f) {
                float e = el_s[i * 16 + 2 * u] + er_s[pj];
                e = e > 0.f ? e : 0.2f * e;
                p0 = __expf(e - m_s[pj]);
            }
            if (a1 > 0.f) {
                float e = el_s[i * 16 + 2 * u + 1] + er_s[pj];
                e = e > 0.f ? e : 0.2f * e;
                p1 = __expf(e - m_s[pj]);
            }
            uint32_t pk = packbf2(p1, p0);
            s_priv += bflo(pk) + bfhi(pk);
            p_buf[u * PPK + pj] = pk;
        }
        __syncthreads();

        const uint32_t* fh = fhi_s + (i % 3) * F_ST;
        const uint32_t* fl = flo_s + (i % 3) * F_ST;
        uint32_t pa[4][4];
#pragma unroll
        for (int mt = 0; mt < 4; mt++) {
            int jb = jm * 64 + mt * 16 + gr;
            const uint32_t* pb = p_buf + tg * PPK + jb;
            pa[mt][0] = pb[0];
            pa[mt][1] = pb[8];
            pa[mt][2] = pb[4 * PPK];
            pa[mt][3] = pb[4 * PPK + 8];
        }
#pragma unroll
        for (int nt = 0; nt < 4; nt++) {
            int db = dn * 32 + nt * 8 + gr;
            uint32_t bh[2], bl[2];
            bh[0] = fh[tg * FPK + db];
            bh[1] = fh[(tg + 4) * FPK + db];
            bl[0] = fl[tg * FPK + db];
            bl[1] = fl[(tg + 4) * FPK + db];
#pragma unroll
            for (int mt = 0; mt < 4; mt++) {
                mma_bf16(acc[mt][nt], pa[mt], bh);
                mma_bf16(acc[mt][nt], pa[mt], bl);
            }
        }

        if (i + 2 < T) issue_stage((i + 2) % 3, i + 2);
        asm volatile("cp.async.commit_group;\n" ::);
    }

    s_red[pj] = s_priv;
    __syncthreads();
#pragma unroll
    for (int t = tid; t < JT; t += 256)
        sc_s[t] = 1.0f / fmaxf(s_red[t], 1e-9f);
    __syncthreads();

    const float* bh_ = bias + (size_t)c * (H * D) + h * D;
#pragma unroll
    for (int mt = 0; mt < 4; mt++) {
#pragma unroll
        for (int nt = 0; nt < 4; nt++) {
            int jl = jm * 64 + mt * 16 + gr;
            int d  = dn * 32 + nt * 8 + tg * 2;
            float bb0 = bh_[d], bb1 = bh_[d + 1];
            float sc0 = sc_s[jl], sc1 = sc_s[jl + 8];
            float o0 = acc[mt][nt][0] * sc0 + bb0;
            float o1 = acc[mt][nt][1] * sc0 + bb1;
            float o2 = acc[mt][nt][2] * sc1 + bb0;
            float o3 = acc[mt][nt][3] * sc1 + bb1;
            if (RELU) {
                o0 = fmaxf(o0, 0.f); o1 = fmaxf(o1, 0.f);
                o2 = fmaxf(o2, 0.f); o3 = fmaxf(o3, 0.f);
            }
            int j = j0 + jl;
            *(float2*)(out + ((size_t)bc * NN + j) * (H * D) + h * D + d)     = make_float2(o0, o1);
            *(float2*)(out + ((size_t)bc * NN + j + 8) * (H * D) + h * D + d) = make_float2(o2, o3);
        }
    }
}

constexpr int AGG_SMEM_64 =
    (NN + 3 * 256 + 8 + 256 + 3 * 16 * 256 + 6 * (8 * 72) + 2 * 8 * 264) * 4;  // 86048

// ---------------- head-mean + channel concat ----------------
__global__ void mean_kernel(const float* __restrict__ in2, float* __restrict__ out) {
    int idx = blockIdx.x * 256 + threadIdx.x;
    if (idx >= B * NN * C * DOUT) return;
    int d = idx % DOUT;
    int c = (idx / DOUT) % C;
    int n = (idx / (DOUT * C)) % NN;
    int b = idx / (DOUT * C * NN);
    const float* p = in2 + ((size_t)(b * C + c) * NN + n) * HD2 + d;
    out[idx] = 0.25f * (p[0] + p[DOUT] + p[2 * DOUT] + p[3 * DOUT]);
}

// ---------------- launch ----------------
extern "C" void kernel_launch(void* const* d_in, const int* in_sizes, int n_in,
                              void* d_out, int out_size) {
    const float* x   = (const float*)d_in[0];
    const float* adj = (const float*)d_in[1];
    const float* W0  = (const float*)d_in[2];
    const float* al0 = (const float*)d_in[3];
    const float* ar0 = (const float*)d_in[4];
    const float* b0  = (const float*)d_in[5];
    const float* W1  = (const float*)d_in[6];
    const float* al1 = (const float*)d_in[7];
    const float* ar1 = (const float*)d_in[8];
    const float* b1  = (const float*)d_in[9];
    const float* W2  = (const float*)d_in[10];
    const float* al2 = (const float*)d_in[11];
    const float* ar2 = (const float*)d_in[12];
    const float* b2  = (const float*)d_in[13];
    float* out = (float*)d_out;

    uint32_t *fhi, *flo, *hhi, *hlo, *xhi, *xlo;
    float *elr, *out2;
    cudaGetSymbolAddress((void**)&fhi,  g_fhi);
    cudaGetSymbolAddress((void**)&flo,  g_flo);
    cudaGetSymbolAddress((void**)&hhi,  g_hhi);
    cudaGetSymbolAddress((void**)&hlo,  g_hlo);
    cudaGetSymbolAddress((void**)&xhi,  g_xhi);
    cudaGetSymbolAddress((void**)&xlo,  g_xlo);
    cudaGetSymbolAddress((void**)&elr,  g_elr);
    cudaGetSymbolAddress((void**)&out2, g_out2);
    float* el = elr;
    float* er = elr + BC * H * NN;

    dim3 t256(256);
    static int attr_set = 0;
    if (!attr_set) {
        cudaFuncSetAttribute(gemm_tc, cudaFuncAttributeMaxDynamicSharedMemorySize, GEMM_SMEM);
        cudaFuncSetAttribute(agg_tc2<true>,
                             cudaFuncAttributeMaxDynamicSharedMemorySize, AGG2_SMEM);
        cudaFuncSetAttribute(agg_tc<DOUT, 256, false>,
                             cudaFuncAttributeMaxDynamicSharedMemorySize, AGG_SMEM_64);
        attr_set = 1;
    }

    size_t elr_bytes = (size_t)2 * BC * H * NN * sizeof(float);

    // ---- prep: pack x[:,0] into d-pair hi/lo ----
    split_x<<<(B * NN * (FIN / 2) + 255) / 256, t256>>>(x, xhi, xlo);

    // ---- layer 0 ----
    cudaMemsetAsync(elr, 0, elr_bytes);
    gemm_tc<<<dim3(HD / 128, NN / 128, BC), t256, GEMM_SMEM>>>(
        xhi, xlo, W0, fhi, flo, FIN, HD, (size_t)NN * (FIN / 2), 0,
        al0, ar0, el, er, DHID);
    agg_tc2<true><<<dim3(NN / 128, H, BC), t256, AGG2_SMEM>>>(
        adj, fhi, flo, el, er, b0, hhi, hlo);

    // ---- layer 1 ----
    cudaMemsetAsync(elr, 0, elr_bytes);
    gemm_tc<<<dim3(HD / 128, NN / 128, BC), t256, GEMM_SMEM>>>(
        hhi, hlo, W1, fhi, flo, HD, HD, (size_t)C * NN * (HD / 2), (size_t)NN * (HD / 2),
        al1, ar1, el, er, DHID);
    agg_tc2<true><<<dim3(NN / 128, H, BC), t256, AGG2_SMEM>>>(
        adj, fhi, flo, el, er, b1, hhi, hlo);

    // ---- layer 2 ----
    cudaMemsetAsync(elr, 0, elr_bytes);
    gemm_tc<<<dim3(HD2 / 128, NN / 128, BC), t256, GEMM_SMEM>>>(
        hhi, hlo, W2, fhi, flo, HD, HD2, (size_t)C * NN * (HD / 2), (size_t)NN * (HD / 2),
        al2, ar2, el, er, DOUT);
    agg_tc<DOUT, 256, false><<<dim3(NN / 256, H, BC), t256, AGG_SMEM_64>>>(
        adj, fhi, flo, el, er, b2, out2);

    // ---- head mean + concat ----
    mean_kernel<<<(B * NN * C * DOUT + 255) / 256, t256>>>(out2, out);
}

// round 15
// speedup vs baseline: 1.0819x; 1.0819x over previous
#include <cuda_runtime.h>
#include <cuda_bf16.h>
#include <cstdint>

// ---------------- problem constants ----------------
constexpr int B    = 8;
constexpr int C    = 5;
constexpr int NN   = 512;
constexpr int FIN  = 768;
constexpr int H    = 4;
constexpr int DHID = 128;
constexpr int DOUT = 64;
constexpr int HD   = H * DHID;   // 512
constexpr int HD2  = H * DOUT;   // 256
constexpr int BC   = B * C;      // 40

// ---------------- scratch ----------------
// i-pair packed feat (gemm out -> agg B): [bc][u=NN/2][Nn<=HD] (hi/lo planes)
__device__ __align__(256) uint32_t g_fhi[(size_t)BC * (NN / 2) * HD];
__device__ __align__(256) uint32_t g_flo[(size_t)BC * (NN / 2) * HD];
// interleaved d-pair packed A (agg out / x): per row, per 16k-chunk: [hi x8 | lo x8]
__device__ __align__(256) uint32_t g_hpk[(size_t)BC * NN * HD];    // width = HD u32
__device__ __align__(256) uint32_t g_xpk[(size_t)B * NN * FIN];    // width = FIN u32
__device__ __align__(256) float g_out2[(size_t)BC * NN * HD2];
__device__ __align__(256) float g_elr [2 * BC * H * NN];

// ---------------- bf16 helpers ----------------
__device__ __forceinline__ uint32_t packbf2(float hi, float lo) {
    uint32_t d;
    asm("cvt.rn.bf16x2.f32 %0, %1, %2;" : "=r"(d) : "f"(hi), "f"(lo));
    return d;
}
__device__ __forceinline__ float bflo(uint32_t u) { return __uint_as_float(u << 16); }
__device__ __forceinline__ float bfhi(uint32_t u) { return __uint_as_float(u & 0xffff0000u); }

__device__ __forceinline__ void mma_bf16(float* d, const uint32_t* a, const uint32_t* b) {
    asm volatile(
        "mma.sync.aligned.m16n8k16.row.col.f32.bf16.bf16.f32 "
        "{%0,%1,%2,%3}, {%4,%5,%6,%7}, {%8,%9}, {%0,%1,%2,%3};\n"
        : "+f"(d[0]), "+f"(d[1]), "+f"(d[2]), "+f"(d[3])
        : "r"(a[0]), "r"(a[1]), "r"(a[2]), "r"(a[3]), "r"(b[0]), "r"(b[1]));
}

__device__ __forceinline__ void cp16(uint32_t smem_dst, const void* gsrc) {
    asm volatile("cp.async.ca.shared.global [%0], [%1], 16;\n"
                 :: "r"(smem_dst), "l"(gsrc));
}

// ---------------- x pre-pack: interleaved d-pair hi/lo ----------------
__global__ void split_x(const float* __restrict__ x, uint32_t* __restrict__ xpk) {
    int idx = blockIdx.x * 256 + threadIdx.x;
    if (idx >= B * NN * (FIN / 2)) return;
    int kp = idx % (FIN / 2);
    int n  = (idx / (FIN / 2)) % NN;
    int b  = idx / (NN * (FIN / 2));
    const float* p = x + ((size_t)b * C * NN + n) * FIN + 2 * kp;
    float v0 = p[0], v1 = p[1];
    uint32_t h = packbf2(v1, v0);
    uint32_t l = packbf2(v1 - bfhi(h), v0 - bflo(h));
    size_t base = ((size_t)b * NN + n) * FIN + (kp >> 3) * 16 + (kp & 7);
    xpk[base]     = h;
    xpk[base + 8] = l;
}

// ---------------- gemm smem geometry ----------------
constexpr int BP    = 132;             // B pitch (f32): (8tg+gr)%32 conflict-free
constexpr int A_STG = 128 * 20;        // A stage (u32), pitch 20: (20gr+tg)%32 c-f
constexpr int STG   = A_STG + 16 * BP; // 4672 u32
constexpr int GEMM_SMEM = 3 * STG * 4; // 56064 B

// ---------------- bf16 GEMM: interleaved pre-packed A, runtime-split W ----------
// out: i-pair packed feat hi/lo + fused el/er.
__global__ __launch_bounds__(256, 2) void gemm_tc(
    const uint32_t* __restrict__ Apk, const float* __restrict__ W,
    uint32_t* __restrict__ Fhi, uint32_t* __restrict__ Flo,
    int K, int Nn, size_t aSB, size_t aSC,
    const float* __restrict__ al, const float* __restrict__ ar,
    float* __restrict__ elo, float* __restrict__ ero, int Dh) {
    extern __shared__ float sm[];

    int bc = blockIdx.z;
    int b  = bc / C, c = bc % C;
    const uint32_t* Ab = Apk + (size_t)b * aSB + (size_t)c * aSC;   // width = K u32
    const float* Wc = W + (size_t)c * K * Nn;
    uint32_t* FhB = Fhi + (size_t)bc * (NN / 2) * Nn;
    uint32_t* FlB = Flo + (size_t)bc * (NN / 2) * Nn;

    int m0 = blockIdx.y * 128, n0c = blockIdx.x * 128;
    int tid  = threadIdx.x;
    int lane = tid & 31, warp = tid >> 5;
    int wm = warp & 1, wn = warp >> 1;
    int gr = lane >> 2, tg = lane & 3;

    uint32_t smem_base = (uint32_t)__cvta_generic_to_shared(sm);

    int arow = tid >> 1, aoff = (tid & 1) * 8;
    int bk0 = tid >> 5,  bnq = (tid & 31) * 4;
    int bk1 = (tid + 256) >> 5;

    auto issue_stage = [&](int st, int t) {
        uint32_t aB = smem_base + (st * STG) * 4;
        uint32_t bB = smem_base + (st * STG + A_STG) * 4;
        const uint32_t* Asrc = Ab + (size_t)(m0 + arow) * K + t * 16 + aoff;
        cp16(aB + (arow * 20 + aoff) * 4, Asrc);
        cp16(aB + (arow * 20 + aoff + 4) * 4, Asrc + 4);
        const float* Wct = Wc + (size_t)(t * 16) * Nn + n0c;
        cp16(bB + (bk0 * BP + bnq) * 4, Wct + (size_t)bk0 * Nn + bnq);
        cp16(bB + (bk1 * BP + bnq) * 4, Wct + (size_t)bk1 * Nn + bnq);
    };

    float acc[4][4][4] = {};

    auto compute_stage = [&](int st) {
        const uint32_t* As = (const uint32_t*)sm + st * STG;
        const float* Bs = (const float*)(As + A_STG);
        uint32_t ah[4][4], alo[4][4], bh[4][2], bl[4][2];
#pragma unroll
        for (int mt = 0; mt < 4; mt++) {
            int m = wm * 64 + mt * 16 + gr;
            ah[mt][0]  = As[m * 20 + tg];
            ah[mt][1]  = As[(m + 8) * 20 + tg];
            ah[mt][2]  = As[m * 20 + tg + 4];
            ah[mt][3]  = As[(m + 8) * 20 + tg + 4];
            alo[mt][0] = As[m * 20 + 8 + tg];
            alo[mt][1] = As[(m + 8) * 20 + 8 + tg];
            alo[mt][2] = As[m * 20 + 12 + tg];
            alo[mt][3] = As[(m + 8) * 20 + 12 + tg];
        }
#pragma unroll
        for (int nt = 0; nt < 4; nt++) {
            int n = wn * 32 + nt * 8 + gr;
            const float* wb = Bs + 2 * tg * BP + n;
            float w0 = wb[0], w1 = wb[BP], w2 = wb[8 * BP], w3 = wb[9 * BP];
            bh[nt][0] = packbf2(w1, w0);
            bh[nt][1] = packbf2(w3, w2);
            bl[nt][0] = packbf2(w1 - bfhi(bh[nt][0]), w0 - bflo(bh[nt][0]));
            bl[nt][1] = packbf2(w3 - bfhi(bh[nt][1]), w2 - bflo(bh[nt][1]));
        }
#pragma unroll
        for (int mt = 0; mt < 4; mt++)
#pragma unroll
            for (int nt = 0; nt < 4; nt++) {
                mma_bf16(acc[mt][nt], ah[mt], bh[nt]);
                mma_bf16(acc[mt][nt], alo[mt], bh[nt]);
                mma_bf16(acc[mt][nt], ah[mt], bl[nt]);
            }
    };

    int T = K / 16;
    issue_stage(0, 0);
    asm volatile("cp.async.commit_group;\n" ::);
    issue_stage(1, 1);
    asm volatile("cp.async.commit_group;\n" ::);

    for (int i = 0; i < T; i++) {
        asm volatile("cp.async.wait_group 1;\n" ::);
        __syncthreads();
        if (i + 2 < T) issue_stage((i + 2) % 3, i + 2);
        asm volatile("cp.async.commit_group;\n" ::);
        compute_stage(i % 3);
    }

    // ---- epilogue: i-pair packed feat + fused el/er ----
    int head  = (n0c + wn * 32) / Dh;
    int dbase = n0c + wn * 32 - head * Dh;
    const float* alh = al + ((size_t)c * H + head) * Dh;
    const float* arh = ar + ((size_t)c * H + head) * Dh;
    float* elh = elo + ((size_t)bc * H + head) * NN;
    float* erh = ero + ((size_t)bc * H + head) * NN;

#pragma unroll
    for (int mt = 0; mt < 4; mt++) {
        float el0 = 0.f, el1 = 0.f, er0 = 0.f, er1 = 0.f;
#pragma unroll
        for (int nt = 0; nt < 4; nt++) {
            float o0 = acc[mt][nt][0], o1 = acc[mt][nt][1];
            float o2 = acc[mt][nt][2], o3 = acc[mt][nt][3];
            float q0 = __shfl_xor_sync(0xffffffffu, o0, 4);
            float q1 = __shfl_xor_sync(0xffffffffu, o1, 4);
            float q2 = __shfl_xor_sync(0xffffffffu, o2, 4);
            float q3 = __shfl_xor_sync(0xffffffffu, o3, 4);
            if (!(gr & 1)) {
                int r = m0 + wm * 64 + mt * 16 + gr;
                int u = r >> 1;
                int col = n0c + wn * 32 + nt * 8 + tg * 2;
                uint32_t h0 = packbf2(q0, o0), h1 = packbf2(q1, o1);
                uint32_t l0 = packbf2(q0 - bfhi(h0), o0 - bflo(h0));
                uint32_t l1 = packbf2(q1 - bfhi(h1), o1 - bflo(h1));
                *(uint2*)(FhB + (size_t)u * Nn + col) = make_uint2(h0, h1);
                *(uint2*)(FlB + (size_t)u * Nn + col) = make_uint2(l0, l1);
                uint32_t h2 = packbf2(q2, o2), h3 = packbf2(q3, o3);
                uint32_t l2 = packbf2(q2 - bfhi(h2), o2 - bflo(h2));
                uint32_t l3 = packbf2(q3 - bfhi(h3), o3 - bflo(h3));
                *(uint2*)(FhB + (size_t)(u + 4) * Nn + col) = make_uint2(h2, h3);
                *(uint2*)(FlB + (size_t)(u + 4) * Nn + col) = make_uint2(l2, l3);
            }
            int d = dbase + nt * 8 + tg * 2;
            float a0 = alh[d], a1 = alh[d + 1];
            float r0 = arh[d], r1 = arh[d + 1];
            el0 += o0 * a0 + o1 * a1;
            el1 += o2 * a0 + o3 * a1;
            er0 += o0 * r0 + o1 * r1;
            er1 += o2 * r0 + o3 * r1;
        }
#pragma unroll
        for (int o = 1; o < 4; o <<= 1) {
            el0 += __shfl_xor_sync(0xffffffffu, el0, o);
            el1 += __shfl_xor_sync(0xffffffffu, el1, o);
            er0 += __shfl_xor_sync(0xffffffffu, er0, o);
            er1 += __shfl_xor_sync(0xffffffffu, er1, o);
        }
        if (tg == 0) {
            int row = m0 + wm * 64 + mt * 16 + gr;
            atomicAdd(elh + row,     el0);
            atomicAdd(elh + row + 8, el1);
            atomicAdd(erh + row,     er0);
            atomicAdd(erh + row + 8, er1);
        }
    }
}

// ================= agg v2 (D=128, JT=128): pre-packed p AND f fragments =================
// out: interleaved d-pair packed (next layer's gemm A).
template <bool RELU>
__global__ __launch_bounds__(256, 2) void agg_tc2(
    const float* __restrict__ adj,
    const uint32_t* __restrict__ fhi_g,
    const uint32_t* __restrict__ flo_g,
    const float* __restrict__ el,
    const float* __restrict__ er,
    const float* __restrict__ bias,
    uint32_t* __restrict__ opk) {
    constexpr int D  = 128, JT = 128;
    constexpr int PPK = 136;
    constexpr int FPK = 136;
    constexpr int ADJ_ST = 16 * JT;
    constexpr int F_ST   = 8 * FPK;
    constexpr int PK_ST  = 8 * PPK;
    constexpr int T = NN / 16;
    constexpr int NC = HD;

    extern __shared__ float sm[];
    float* el_s  = sm;
    float* er_s  = el_s + NN;
    float* m_s   = er_s + JT;
    float* sc_s  = m_s + JT;
    float* red   = sc_s + JT;
    float* s_red = red + 8;
    float* adj_s = s_red + 2 * JT;
    uint32_t* fhi_s = (uint32_t*)(adj_s + 4 * ADJ_ST);
    uint32_t* flo_s = fhi_s + 4 * F_ST;
    uint32_t* p_pk  = flo_s + 4 * F_ST;

    int bc = blockIdx.z, h = blockIdx.y;
    int c = bc % C;
    int j0 = blockIdx.x * JT;
    int tid = threadIdx.x;
    int lane = tid & 31, warp = tid >> 5;
    int jm = warp & 1, dn = warp >> 1;
    int gr = lane >> 2, tg = lane & 3;

    const float* adj_bc = adj + (size_t)bc * NN * NN;
    const float* elh = el + (size_t)(bc * H + h) * NN;
    const float* erh = er + (size_t)(bc * H + h) * NN;
    const uint32_t* fh_g = fhi_g + (size_t)bc * (NN / 2) * NC + h * D;
    const uint32_t* fl_g = flo_g + (size_t)bc * (NN / 2) * NC + h * D;

    uint32_t smem_u32 = (uint32_t)__cvta_generic_to_shared(sm);
    uint32_t adj_u32  = smem_u32 + (uint32_t)((adj_s - sm) * 4);
    uint32_t fhi_u32  = smem_u32 + (uint32_t)((float*)fhi_s - sm) * 4;
    uint32_t flo_u32  = smem_u32 + (uint32_t)((float*)flo_s - sm) * 4;

    auto issue_stage = [&](int st, int t) {
        uint32_t aB = adj_u32 + st * ADJ_ST * 4;
#pragma unroll
        for (int l = 0; l < 2; l++) {
            int s = tid + l * 256;
            int r = s >> 5, cq = s & 31;
            cp16(aB + (r * JT + cq * 4) * 4,
                 adj_bc + (size_t)(t * 16 + r) * NN + j0 + cq * 4);
        }
        {
            int r = tid >> 5, cq = tid & 31;
            size_t g = (size_t)(t * 8 + r) * NC + cq * 4;
            cp16(fhi_u32 + (st * F_ST + r * FPK + cq * 4) * 4, fh_g + g);
            cp16(flo_u32 + (st * F_ST + r * FPK + cq * 4) * 4, fl_g + g);
        }
    };

    float e0 = elh[tid], e1 = elh[tid + 256];
    el_s[tid] = e0; el_s[tid + 256] = e1;
    if (tid < JT) er_s[tid] = erh[j0 + tid];

    issue_stage(0, 0);
    asm volatile("cp.async.commit_group;\n" ::);
    issue_stage(1, 1);
    asm volatile("cp.async.commit_group;\n" ::);
    issue_stage(2, 2);
    asm volatile("cp.async.commit_group;\n" ::);

    float v = fmaxf(e0, e1);
#pragma unroll
    for (int o = 16; o; o >>= 1) v = fmaxf(v, __shfl_xor_sync(0xffffffffu, v, o));
    if (lane == 0) red[warp] = v;
    __syncthreads();
    if (tid == 0) {
        float m = red[0];
#pragma unroll
        for (int w = 1; w < 8; w++) m = fmaxf(m, red[w]);
        red[0] = m;
    }
    __syncthreads();
    if (tid < JT) {
        float e = red[0] + er_s[tid];
        m_s[tid] = e > 0.f ? e : 0.2f * e;
    }

    int pj  = tid % JT;
    int pi0 = tid / JT;
    float s_priv = 0.f;

    auto produce = [&](int t) {
        const float* a_st = adj_s + (t % 4) * ADJ_ST;
        uint32_t* p_nb = p_pk + (t & 1) * PK_ST;
#pragma unroll
        for (int q = 0; q < 4; q++) {
            int u = pi0 * 4 + q;
            float a0 = a_st[(2 * u) * JT + pj];
            float a1 = a_st[(2 * u + 1) * JT + pj];
            float p0 = 0.f, p1 = 0.f;
            if (a0 > 0.f) {
                float e = el_s[t * 16 + 2 * u] + er_s[pj];
                e = e > 0.f ? e : 0.2f * e;
                p0 = __expf(e - m_s[pj]);
            }
            if (a1 > 0.f) {
                float e = el_s[t * 16 + 2 * u + 1] + er_s[pj];
                e = e > 0.f ? e : 0.2f * e;
                p1 = __expf(e - m_s[pj]);
            }
            uint32_t pk = packbf2(p1, p0);
            s_priv += bflo(pk) + bfhi(pk);
            p_nb[u * PPK + pj] = pk;
        }
    };

    asm volatile("cp.async.wait_group 2;\n" ::);
    __syncthreads();
    produce(0);

    float acc[4][4][4] = {};

    for (int i = 0; i < T; i++) {
        asm volatile("cp.async.wait_group 1;\n" ::);
        __syncthreads();

        const uint32_t* fh = fhi_s + (i % 4) * F_ST;
        const uint32_t* fl = flo_s + (i % 4) * F_ST;
        const uint32_t* p_buf = p_pk + (i & 1) * PK_ST;

        uint32_t pa[4][4];
#pragma unroll
        for (int mt = 0; mt < 4; mt++) {
            int jb = jm * 64 + mt * 16 + gr;
            const uint32_t* pb = p_buf + tg * PPK + jb;
            pa[mt][0] = pb[0];
            pa[mt][1] = pb[8];
            pa[mt][2] = pb[4 * PPK];
            pa[mt][3] = pb[4 * PPK + 8];
        }
#pragma unroll
        for (int nt = 0; nt < 4; nt++) {
            int db = dn * 32 + nt * 8 + gr;
            uint32_t bh[2], bl[2];
            bh[0] = fh[tg * FPK + db];
            bh[1] = fh[(tg + 4) * FPK + db];
            bl[0] = fl[tg * FPK + db];
            bl[1] = fl[(tg + 4) * FPK + db];
#pragma unroll
            for (int mt = 0; mt < 4; mt++) {
                mma_bf16(acc[mt][nt], pa[mt], bh);
                mma_bf16(acc[mt][nt], pa[mt], bl);
            }
        }

        if (i + 1 < T) produce(i + 1);

        if (i + 3 < T) issue_stage((i + 3) % 4, i + 3);
        asm volatile("cp.async.commit_group;\n" ::);
    }

    s_red[pi0 * JT + pj] = s_priv;
    __syncthreads();
    if (tid < JT)
        sc_s[tid] = 1.0f / fmaxf(s_red[tid] + s_red[JT + tid], 1e-9f);
    __syncthreads();

    // ---- epilogue: interleaved d-pair packed output ----
    uint32_t* ob = opk + (size_t)bc * NN * HD;
    const float* bh_ = bias + (size_t)c * (H * D) + h * D;
    int kpb = h * (D / 2);
#pragma unroll
    for (int mt = 0; mt < 4; mt++) {
#pragma unroll
        for (int nt = 0; nt < 4; nt++) {
            int jl = jm * 64 + mt * 16 + gr;
            int d  = dn * 32 + nt * 8 + tg * 2;
            float bb0 = bh_[d], bb1 = bh_[d + 1];
            float sc0 = sc_s[jl], sc1 = sc_s[jl + 8];
            float o0 = acc[mt][nt][0] * sc0 + bb0;
            float o1 = acc[mt][nt][1] * sc0 + bb1;
            float o2 = acc[mt][nt][2] * sc1 + bb0;
            float o3 = acc[mt][nt][3] * sc1 + bb1;
            if (RELU) {
                o0 = fmaxf(o0, 0.f); o1 = fmaxf(o1, 0.f);
                o2 = fmaxf(o2, 0.f); o3 = fmaxf(o3, 0.f);
            }
            int kp = kpb + (d >> 1);
            int ch = kp >> 3, w = kp & 7;
            int j = j0 + jl;
            uint32_t h0 = packbf2(o1, o0);
            uint32_t h1 = packbf2(o3, o2);
            size_t base0 = (size_t)j * HD + ch * 16 + w;
            size_t base1 = (size_t)(j + 8) * HD + ch * 16 + w;
            ob[base0]     = h0;
            ob[base0 + 8] = packbf2(o1 - bfhi(h0), o0 - bflo(h0));
            ob[base1]     = h1;
            ob[base1 + 8] = packbf2(o3 - bfhi(h1), o2 - bflo(h1));
        }
    }
}

constexpr int AGG2_SMEM =
    (NN + 3 * 128 + 8 + 2 * 128 + 4 * 16 * 128 + 8 * (8 * 136) + 2 * 8 * 136) * 4;  // 80928

// ================= agg v1 (layer 2: D=64, JT=256): packed p + packed f, f32 out ==========
template <int D, int JT, bool RELU>
__global__ __launch_bounds__(256) void agg_tc(
    const float* __restrict__ adj,
    const uint32_t* __restrict__ fhi_g,
    const uint32_t* __restrict__ flo_g,
    const float* __restrict__ el,
    const float* __restrict__ er,
    const float* __restrict__ bias,
    float* __restrict__ out) {
    constexpr int PPK = JT + 8;       // 264
    constexpr int FPK = D + 8;        // 72
    constexpr int WJ = JT / 64;
    constexpr int ADJ_ST = 16 * JT;
    constexpr int F_ST   = 8 * FPK;
    constexpr int PK_ST  = 8 * PPK;
    constexpr int NC = HD2;

    extern __shared__ float sm[];
    float* el_s  = sm;
    float* er_s  = el_s + NN;
    float* m_s   = er_s + JT;
    float* sc_s  = m_s + JT;
    float* red   = sc_s + JT;
    float* s_red = red + 8;
    float* adj_s = s_red + JT;
    uint32_t* fhi_s = (uint32_t*)(adj_s + 3 * ADJ_ST);
    uint32_t* flo_s = fhi_s + 3 * F_ST;
    uint32_t* p_pk  = flo_s + 3 * F_ST;

    int bc = blockIdx.z, h = blockIdx.y;
    int c = bc % C;
    int j0 = blockIdx.x * JT;
    int tid = threadIdx.x;
    int lane = tid & 31, warp = tid >> 5;
    int jm = warp % WJ, dn = warp / WJ;
    int gr = lane >> 2, tg = lane & 3;

    const float* adj_bc = adj + (size_t)bc * NN * NN;
    const float* elh = el + (size_t)(bc * H + h) * NN;
    const float* erh = er + (size_t)(bc * H + h) * NN;
    const uint32_t* fh_g = fhi_g + (size_t)bc * (NN / 2) * NC + h * D;
    const uint32_t* fl_g = flo_g + (size_t)bc * (NN / 2) * NC + h * D;

    uint32_t smem_u32 = (uint32_t)__cvta_generic_to_shared(sm);
    uint32_t adj_u32  = smem_u32 + (uint32_t)((adj_s - sm) * 4);
    uint32_t fhi_u32  = smem_u32 + (uint32_t)((float*)fhi_s - sm) * 4;
    uint32_t flo_u32  = smem_u32 + (uint32_t)((float*)flo_s - sm) * 4;

    auto issue_stage = [&](int st, int t) {
        uint32_t aB = adj_u32 + st * ADJ_ST * 4;
#pragma unroll
        for (int l = 0; l < 4; l++) {
            int s = tid + l * 256;
            int r = s >> 6, cq = s & 63;
            cp16(aB + (r * JT + cq * 4) * 4,
                 adj_bc + (size_t)(t * 16 + r) * NN + j0 + cq * 4);
        }
        {
            int s = tid & 127;
            int r = s >> 4, cq = s & 15;
            size_t g = (size_t)(t * 8 + r) * NC + cq * 4;
            if (tid < 128)
                cp16(fhi_u32 + (st * F_ST + r * FPK + cq * 4) * 4, fh_g + g);
            else
                cp16(flo_u32 + (st * F_ST + r * FPK + cq * 4) * 4, fl_g + g);
        }
    };

    float e0 = elh[tid], e1 = elh[tid + 256];
    el_s[tid] = e0; el_s[tid + 256] = e1;
#pragma unroll
    for (int t = tid; t < JT; t += 256) er_s[t] = erh[j0 + t];

    issue_stage(0, 0);
    asm volatile("cp.async.commit_group;\n" ::);
    issue_stage(1, 1);
    asm volatile("cp.async.commit_group;\n" ::);

    float v = fmaxf(e0, e1);
#pragma unroll
    for (int o = 16; o; o >>= 1) v = fmaxf(v, __shfl_xor_sync(0xffffffffu, v, o));
    if (lane == 0) red[warp] = v;
    __syncthreads();
    if (tid == 0) {
        float m = red[0];
#pragma unroll
        for (int w = 1; w < 8; w++) m = fmaxf(m, red[w]);
        red[0] = m;
    }
    __syncthreads();
#pragma unroll
    for (int t = tid; t < JT; t += 256) {
        float e = red[0] + er_s[t];
        m_s[t] = e > 0.f ? e : 0.2f * e;
    }

    int pj = tid;   // JT == 256

    float acc[4][4][4] = {};
    float s_priv = 0.f;

    constexpr int T = NN / 16;
    for (int i = 0; i < T; i++) {
        asm volatile("cp.async.wait_group 1;\n" ::);
        __syncthreads();

        const float* a_st = adj_s + (i % 3) * ADJ_ST;
        uint32_t* p_buf = p_pk + (i & 1) * PK_ST;
#pragma unroll
        for (int u = 0; u < 8; u++) {
            float a0 = a_st[(2 * u) * JT + pj];
            float a1 = a_st[(2 * u + 1) * JT + pj];
            float p0 = 0.f, p1 = 0.f;
            if (a0 > 0.f) {
                float e = el_s[i * 16 + 2 * u] + er_s[pj];
                e = e > 0.f ? e : 0.2f * e;
                p0 = __expf(e - m_s[pj]);
            }
            if (a1 > 0.f) {
                float e = el_s[i * 16 + 2 * u + 1] + er_s[pj];
                e = e > 0.f ? e : 0.2f * e;
                p1 = __expf(e - m_s[pj]);
            }
            uint32_t pk = packbf2(p1, p0);
            s_priv += bflo(pk) + bfhi(pk);
            p_buf[u * PPK + pj] = pk;
        }
        __syncthreads();

        const uint32_t* fh = fhi_s + (i % 3) * F_ST;
        const uint32_t* fl = flo_s + (i % 3) * F_ST;
        uint32_t pa[4][4];
#pragma unroll
        for (int mt = 0; mt < 4; mt++) {
            int jb = jm * 64 + mt * 16 + gr;
            const uint32_t* pb = p_buf + tg * PPK + jb;
            pa[mt][0] = pb[0];
            pa[mt][1] = pb[8];
            pa[mt][2] = pb[4 * PPK];
            pa[mt][3] = pb[4 * PPK + 8];
        }
#pragma unroll
        for (int nt = 0; nt < 4; nt++) {
            int db = dn * 32 + nt * 8 + gr;
            uint32_t bh[2], bl[2];
            bh[0] = fh[tg * FPK + db];
            bh[1] = fh[(tg + 4) * FPK + db];
            bl[0] = fl[tg * FPK + db];
            bl[1] = fl[(tg + 4) * FPK + db];
#pragma unroll
            for (int mt = 0; mt < 4; mt++) {
                mma_bf16(acc[mt][nt], pa[mt], bh);
                mma_bf16(acc[mt][nt], pa[mt], bl);
            }
        }

        if (i + 2 < T) issue_stage((i + 2) % 3, i + 2);
        asm volatile("cp.async.commit_group;\n" ::);
    }

    s_red[pj] = s_priv;
    __syncthreads();
#pragma unroll
    for (int t = tid; t < JT; t += 256)
        sc_s[t] = 1.0f / fmaxf(s_red[t], 1e-9f);
    __syncthreads();

    const float* bh_ = bias + (size_t)c * (H * D) + h * D;
#pragma unroll
    for (int mt = 0; mt < 4; mt++) {
#pragma unroll
        for (int nt = 0; nt < 4; nt++) {
            int jl = jm * 64 + mt * 16 + gr;
            int d  = dn * 32 + nt * 8 + tg * 2;
            float bb0 = bh_[d], bb1 = bh_[d + 1];
            float sc0 = sc_s[jl], sc1 = sc_s[jl + 8];
            float o0 = acc[mt][nt][0] * sc0 + bb0;
            float o1 = acc[mt][nt][1] * sc0 + bb1;
            float o2 = acc[mt][nt][2] * sc1 + bb0;
            float o3 = acc[mt][nt][3] * sc1 + bb1;
            if (RELU) {
                o0 = fmaxf(o0, 0.f); o1 = fmaxf(o1, 0.f);
                o2 = fmaxf(o2, 0.f); o3 = fmaxf(o3, 0.f);
            }
            int j = j0 + jl;
            *(float2*)(out + ((size_t)bc * NN + j) * (H * D) + h * D + d)     = make_float2(o0, o1);
            *(float2*)(out + ((size_t)bc * NN + j + 8) * (H * D) + h * D + d) = make_float2(o2, o3);
        }
    }
}

constexpr int AGG_SMEM_64 =
    (NN + 3 * 256 + 8 + 256 + 3 * 16 * 256 + 6 * (8 * 72) + 2 * 8 * 264) * 4;  // 86048

// ---------------- head-mean + channel concat ----------------
__global__ void mean_kernel(const float* __restrict__ in2, float* __restrict__ out) {
    int idx = blockIdx.x * 256 + threadIdx.x;
    if (idx >= B * NN * C * DOUT) return;
    int d = idx % DOUT;
    int c = (idx / DOUT) % C;
    int n = (idx / (DOUT * C)) % NN;
    int b = idx / (DOUT * C * NN);
    const float* p = in2 + ((size_t)(b * C + c) * NN + n) * HD2 + d;
    out[idx] = 0.25f * (p[0] + p[DOUT] + p[2 * DOUT] + p[3 * DOUT]);
}

// ---------------- launch ----------------
extern "C" void kernel_launch(void* const* d_in, const int* in_sizes, int n_in,
                              void* d_out, int out_size) {
    const float* x   = (const float*)d_in[0];
    const float* adj = (const float*)d_in[1];
    const float* W0  = (const float*)d_in[2];
    const float* al0 = (const float*)d_in[3];
    const float* ar0 = (const float*)d_in[4];
    const float* b0  = (const float*)d_in[5];
    const float* W1  = (const float*)d_in[6];
    const float* al1 = (const float*)d_in[7];
    const float* ar1 = (const float*)d_in[8];
    const float* b1  = (const float*)d_in[9];
    const float* W2  = (const float*)d_in[10];
    const float* al2 = (const float*)d_in[11];
    const float* ar2 = (const float*)d_in[12];
    const float* b2  = (const float*)d_in[13];
    float* out = (float*)d_out;

    uint32_t *fhi, *flo, *hpk, *xpk;
    float *elr, *out2;
    cudaGetSymbolAddress((void**)&fhi,  g_fhi);
    cudaGetSymbolAddress((void**)&flo,  g_flo);
    cudaGetSymbolAddress((void**)&hpk,  g_hpk);
    cudaGetSymbolAddress((void**)&xpk,  g_xpk);
    cudaGetSymbolAddress((void**)&elr,  g_elr);
    cudaGetSymbolAddress((void**)&out2, g_out2);
    float* el = elr;
    float* er = elr + BC * H * NN;

    dim3 t256(256);
    static int attr_set = 0;
    if (!attr_set) {
        cudaFuncSetAttribute(gemm_tc, cudaFuncAttributeMaxDynamicSharedMemorySize, GEMM_SMEM);
        cudaFuncSetAttribute(agg_tc2<true>,
                             cudaFuncAttributeMaxDynamicSharedMemorySize, AGG2_SMEM);
        cudaFuncSetAttribute(agg_tc<DOUT, 256, false>,
                             cudaFuncAttributeMaxDynamicSharedMemorySize, AGG_SMEM_64);
        attr_set = 1;
    }

    size_t elr_bytes = (size_t)2 * BC * H * NN * sizeof(float);

    // ---- prep: pack x[:,0] into interleaved d-pair hi/lo ----
    split_x<<<(B * NN * (FIN / 2) + 255) / 256, t256>>>(x, xpk);

    // ---- layer 0 ----
    cudaMemsetAsync(elr, 0, elr_bytes);
    gemm_tc<<<dim3(HD / 128, NN / 128, BC), t256, GEMM_SMEM>>>(
        xpk, W0, fhi, flo, FIN, HD, (size_t)NN * FIN, 0,
        al0, ar0, el, er, DHID);
    agg_tc2<true><<<dim3(NN / 128, H, BC), t256, AGG2_SMEM>>>(
        adj, fhi, flo, el, er, b0, hpk);

    // ---- layer 1 ----
    cudaMemsetAsync(elr, 0, elr_bytes);
    gemm_tc<<<dim3(HD / 128, NN / 128, BC), t256, GEMM_SMEM>>>(
        hpk, W1, fhi, flo, HD, HD, (size_t)C * NN * HD, (size_t)NN * HD,
        al1, ar1, el, er, DHID);
    agg_tc2<true><<<dim3(NN / 128, H, BC), t256, AGG2_SMEM>>>(
        adj, fhi, flo, el, er, b1, hpk);

    // ---- layer 2 ----
    cudaMemsetAsync(elr, 0, elr_bytes);
    gemm_tc<<<dim3(HD2 / 128, NN / 128, BC), t256, GEMM_SMEM>>>(
        hpk, W2, fhi, flo, HD, HD2, (size_t)C * NN * HD, (size_t)NN * HD,
        al2, ar2, el, er, DOUT);
    agg_tc<DOUT, 256, false><<<dim3(NN / 256, H, BC), t256, AGG_SMEM_64>>>(
        adj, fhi, flo, el, er, b2, out2);

    // ---- head mean + concat ----
    mean_kernel<<<(B * NN * C * DOUT + 255) / 256, t256>>>(out2, out);
}